// round 4
// baseline (speedup 1.0000x reference)
#include <cuda_runtime.h>
#include <cuda_bf16.h>

#define KK 7
#define C1 21
#define NBINS 49            // KK*KK
#define NCH 1029            // NBINS*C1
#define HF 128
#define WF 128
#define PLANE (HF*WF)       // 16384
#define FEAT_STRIDE 30

// P layout: [g][y][slot][cc] with slot = x+1 (slot 0 is an all-zero column so
// the left-corner read at xs=0 needs no predication).
// ROWP = row stride in floats: 129*21 = 2709, padded to 2712 (float4 multiple)
#define ROWP 2712
#define PLANEP (HF*ROWP)    // 347136 floats per bin-group

// 49 * 347136 floats ~ 68.0 MB scratch
__device__ float g_prefix[NBINS * PLANEP];

// ---------------------------------------------------------------------------
// K1: NCHW -> [g][y][x+1][cc] transpose fused with inclusive x-prefix-sum.
// One block per (g, y), 256 threads (8 warps). Warp w scans class rows
// cc = w, w+8, ... in registers (LDG.128 + local chain + warp shuffle scan),
// scatters transposed into smem, then the block streams 678 float4 out.
// ---------------------------------------------------------------------------
__global__ __launch_bounds__(256)
void psroi_transpose_scan_kernel(const float* __restrict__ fmap,
                                 float* __restrict__ P)
{
    const int g = blockIdx.x >> 7;        // 0..48
    const int y = blockIdx.x & 127;       // 0..127
    const int t = threadIdx.x;
    const int warp = t >> 5;
    const int lane = t & 31;

    __shared__ float tile2[ROWP];         // [(x+1)*21 + cc]

    // zero column (slots 0..20) + tail pad (2709..2711)
    if (t < C1) tile2[t] = 0.0f;
    if (t >= 32 && t < 35) tile2[ROWP - 3 + (t - 32)] = 0.0f;

    for (int cc = warp; cc < C1; cc += 8) {
        const float4* src = (const float4*)(fmap + (size_t)(g * C1 + cc) * PLANE + y * WF);
        float4 v = __ldg(src + lane);
        float a0 = v.x;
        float a1 = a0 + v.y;
        float a2 = a1 + v.z;
        float a3 = a2 + v.w;
        float s = a3;
        #pragma unroll
        for (int d = 1; d < 32; d <<= 1) {
            float u = __shfl_up_sync(0xffffffff, s, d);
            if (lane >= d) s += u;
        }
        float excl = __shfl_up_sync(0xffffffff, s, 1);
        if (lane == 0) excl = 0.0f;

        const int slot = 4 * lane + 1;    // x+1
        tile2[(slot + 0) * C1 + cc] = excl + a0;
        tile2[(slot + 1) * C1 + cc] = excl + a1;
        tile2[(slot + 2) * C1 + cc] = excl + a2;
        tile2[(slot + 3) * C1 + cc] = excl + a3;
    }
    __syncthreads();

    float4* dst4 = (float4*)(P + (size_t)g * PLANEP + y * ROWP);
    const float4* s4 = (const float4*)tile2;
    #pragma unroll
    for (int i = t; i < ROWP / 4; i += 256)
        dst4[i] = s4[i];
}

// ---------------------------------------------------------------------------
// K2: pooling + mean + softmax. One block per ROI, 1024 threads.
// Thread t handles flat channel c = t (+1024): c = g*21 + cc. 21 adjacent
// lanes read 84B-contiguous corner columns. Left corner reads the zero
// column when xs==0 -> branch-free inner loop:
//   acc += P[right] - P[left];  right += ROWP; left += ROWP;
// ---------------------------------------------------------------------------
__global__ __launch_bounds__(1024)
void psroi_pool_kernel(const float* __restrict__ P,
                       const int* __restrict__ rois,
                       float* __restrict__ out)
{
    const int n = blockIdx.x;
    const int t = threadIdx.x;

    __shared__ float pool[NCH];

    const int4 rr = ((const int4*)rois)[n];
    const int ymin = rr.x / FEAT_STRIDE;
    const int xmin = rr.y / FEAT_STRIDE;
    const int ymax = rr.z / FEAT_STRIDE;
    const int xmax = rr.w / FEAT_STRIDE;
    const int ystep = (ymax - ymin) / KK;
    const int xstep = (xmax - xmin) / KK;
    const bool has_area = (ystep > 0) && (xstep > 0);
    const float inv_area = has_area ? (1.0f / (float)(ystep * xstep)) : 0.0f;

    for (int c = t; c < NCH; c += 1024) {
        const int g  = c / C1;
        const int cc = c - g * C1;
        const int j  = g / KK;
        const int l  = g - j * KK;
        const int ys = ymin + j * ystep;
        const int xs = xmin + l * xstep;
        const int xe = xs + xstep;        // right corner slot (= (xe-1)+1)

        float acc = 0.0f;
        if (has_area) {
            const float* pr = P + (size_t)g * PLANEP + ys * ROWP + xe * C1 + cc;
            const float* pl = pr - xstep * C1;   // left corner slot = xs
            for (int dy = 0; dy < ystep; ++dy) {
                acc += __ldg(pr) - __ldg(pl);
                pr += ROWP;
                pl += ROWP;
            }
            acc *= inv_area;
        }
        pool[c] = acc;
    }
    __syncthreads();

    // Per-class mean over 49 bins + softmax over 21 classes (warp 0 only)
    if (t < 32) {
        float v = -1e30f;
        if (t < C1) {
            float s = 0.0f;
            #pragma unroll
            for (int g = 0; g < NBINS; ++g)
                s += pool[g * C1 + t];
            v = s * (1.0f / (float)NBINS);
        }
        float mx = v;
        #pragma unroll
        for (int o = 16; o; o >>= 1)
            mx = fmaxf(mx, __shfl_xor_sync(0xffffffff, mx, o));
        float e = (t < C1) ? __expf(v - mx) : 0.0f;
        float sm = e;
        #pragma unroll
        for (int o = 16; o; o >>= 1)
            sm += __shfl_xor_sync(0xffffffff, sm, o);
        if (t < C1)
            out[n * C1 + t] = e / sm;
    }
}

extern "C" void kernel_launch(void* const* d_in, const int* in_sizes, int n_in,
                              void* d_out, int out_size)
{
    const float* fmap = (const float*)d_in[0];   // (1, 1029, 128, 128) fp32
    const int*   rois = (const int*)d_in[1];     // (N, 4) int32
    float* out = (float*)d_out;                  // (N, 21) fp32
    const int n_rois = in_sizes[1] / 4;

    float* P;
    cudaGetSymbolAddress((void**)&P, g_prefix);

    psroi_transpose_scan_kernel<<<NBINS * HF, 256>>>(fmap, P);
    psroi_pool_kernel<<<n_rois, 1024>>>(P, rois, out);
}

// round 5
// speedup vs baseline: 1.1144x; 1.1144x over previous
#include <cuda_runtime.h>
#include <cuda_bf16.h>

#define KK 7
#define C1 21
#define NBINS 49            // KK*KK
#define NCH 1029            // NBINS*C1
#define HF 128
#define WF 128
#define PLANE (HF*WF)       // 16384
#define FEAT_STRIDE 30
#define MAX_YSTEP 9         // rois: (ymax-ymin) <= 63 -> ystep <= 9

// P layout: [g][y][slot][cc] with slot = x+1 (slot 0 is an all-zero column so
// the left-corner read at xs=0 needs no predication).
#define ROWP 2712           // 129*21 = 2709 padded to float4 multiple
#define PLANEP (HF*ROWP)    // 347136 floats per bin-group

// 49 * 347136 floats ~ 68.0 MB scratch
__device__ float g_prefix[NBINS * PLANEP];

// ---------------------------------------------------------------------------
// K1: NCHW -> [g][y][x+1][cc] transpose fused with inclusive x-prefix-sum.
// One block per (g, y), 256 threads (8 warps). Register-resident warp scan,
// transpose via smem, contiguous float4 stream out.
// ---------------------------------------------------------------------------
__global__ __launch_bounds__(256)
void psroi_transpose_scan_kernel(const float* __restrict__ fmap,
                                 float* __restrict__ P)
{
    const int g = blockIdx.x >> 7;        // 0..48
    const int y = blockIdx.x & 127;       // 0..127
    const int t = threadIdx.x;
    const int warp = t >> 5;
    const int lane = t & 31;

    __shared__ float tile2[ROWP];         // [(x+1)*21 + cc]

    if (t < C1) tile2[t] = 0.0f;                               // zero column
    if (t >= 32 && t < 35) tile2[ROWP - 3 + (t - 32)] = 0.0f;  // tail pad

    for (int cc = warp; cc < C1; cc += 8) {
        const float4* src = (const float4*)(fmap + (size_t)(g * C1 + cc) * PLANE + y * WF);
        float4 v = __ldg(src + lane);
        float a0 = v.x;
        float a1 = a0 + v.y;
        float a2 = a1 + v.z;
        float a3 = a2 + v.w;
        float s = a3;
        #pragma unroll
        for (int d = 1; d < 32; d <<= 1) {
            float u = __shfl_up_sync(0xffffffff, s, d);
            if (lane >= d) s += u;
        }
        float excl = __shfl_up_sync(0xffffffff, s, 1);
        if (lane == 0) excl = 0.0f;

        const int slot = 4 * lane + 1;    // x+1
        tile2[(slot + 0) * C1 + cc] = excl + a0;
        tile2[(slot + 1) * C1 + cc] = excl + a1;
        tile2[(slot + 2) * C1 + cc] = excl + a2;
        tile2[(slot + 3) * C1 + cc] = excl + a3;
    }
    __syncthreads();

    float4* dst4 = (float4*)(P + (size_t)g * PLANEP + y * ROWP);
    const float4* s4 = (const float4*)tile2;
    #pragma unroll
    for (int i = t; i < ROWP / 4; i += 256)
        dst4[i] = s4[i];
}

// ---------------------------------------------------------------------------
// K2: pooling + mean + softmax. One block per ROI, 1024 threads.
// Thread = flat channel c = g*21+cc. 32-bit indexing throughout; dy loop
// fully unrolled (<= MAX_YSTEP) with predication so all corner loads are
// immediate-offset LDGs batched in flight (MLP ~18).
// ---------------------------------------------------------------------------
__global__ __launch_bounds__(1024)
void psroi_pool_kernel(const float* __restrict__ P,
                       const int* __restrict__ rois,
                       float* __restrict__ out)
{
    const int n = blockIdx.x;
    const int t = threadIdx.x;

    __shared__ float pool[NCH];

    const int4 rr = __ldg(((const int4*)rois) + n);
    const unsigned ymin = (unsigned)rr.x / FEAT_STRIDE;
    const unsigned xmin = (unsigned)rr.y / FEAT_STRIDE;
    const unsigned ymax = (unsigned)rr.z / FEAT_STRIDE;
    const unsigned xmax = (unsigned)rr.w / FEAT_STRIDE;
    const int ystep = (int)((ymax - ymin) / KK);
    const int xstep = (int)((xmax - xmin) / KK);
    const bool has_area = (ystep > 0) && (xstep > 0);
    const float inv_area = has_area ? (1.0f / (float)(ystep * xstep)) : 0.0f;

    for (unsigned c = t; c < NCH; c += 1024) {
        const unsigned g  = c / C1;
        const unsigned cc = c - g * C1;
        const unsigned j  = g / KK;
        const unsigned l  = g - j * KK;
        const unsigned ys = ymin + j * ystep;
        const unsigned xs = xmin + l * xstep;
        const unsigned xe = xs + xstep;    // right corner slot index

        float acc = 0.0f;
        if (has_area) {
            const unsigned offR = g * PLANEP + ys * ROWP + xe * C1 + cc;
            const unsigned offL = offR - (unsigned)(xstep * C1);  // left slot = xs
            #pragma unroll
            for (int dy = 0; dy < MAX_YSTEP; ++dy) {
                if (dy < ystep)
                    acc += __ldg(P + offR + dy * ROWP) - __ldg(P + offL + dy * ROWP);
            }
            acc *= inv_area;
        }
        pool[c] = acc;
    }
    __syncthreads();

    // Per-class mean over 49 bins + softmax over 21 classes (warp 0 only)
    if (t < 32) {
        float v = -1e30f;
        if (t < C1) {
            float s = 0.0f;
            #pragma unroll
            for (int g = 0; g < NBINS; ++g)
                s += pool[g * C1 + t];
            v = s * (1.0f / (float)NBINS);
        }
        float mx = v;
        #pragma unroll
        for (int o = 16; o; o >>= 1)
            mx = fmaxf(mx, __shfl_xor_sync(0xffffffff, mx, o));
        float e = (t < C1) ? __expf(v - mx) : 0.0f;
        float sm = e;
        #pragma unroll
        for (int o = 16; o; o >>= 1)
            sm += __shfl_xor_sync(0xffffffff, sm, o);
        if (t < C1)
            out[n * C1 + t] = e / sm;
    }
}

extern "C" void kernel_launch(void* const* d_in, const int* in_sizes, int n_in,
                              void* d_out, int out_size)
{
    const float* fmap = (const float*)d_in[0];   // (1, 1029, 128, 128) fp32
    const int*   rois = (const int*)d_in[1];     // (N, 4) int32
    float* out = (float*)d_out;                  // (N, 21) fp32
    const int n_rois = in_sizes[1] / 4;

    float* P;
    cudaGetSymbolAddress((void**)&P, g_prefix);

    psroi_transpose_scan_kernel<<<NBINS * HF, 256>>>(fmap, P);
    psroi_pool_kernel<<<n_rois, 1024>>>(P, rois, out);
}